// round 12
// baseline (speedup 1.0000x reference)
#include <cuda_runtime.h>
#include <cstdint>

#define Bc 4
#define Cc 256
#define Nn 4096

__device__ float g_Qhi[Bc*Nn*32];
__device__ float g_Qlo[Bc*Nn*32];
__device__ float g_Khi[Bc*Nn*32];
__device__ float g_Klo[Bc*Nn*32];
__device__ float g_Vt[(size_t)Bc*Cc*Nn];   // [b][c][n], tf32-rounded

__device__ __forceinline__ float tf32r(float x){
    uint32_t u; asm("cvt.rna.tf32.f32 %0, %1;" : "=r"(u) : "f"(x));
    return __uint_as_float(u);
}
__device__ __forceinline__ void mma8(float d[4], const uint32_t a[4], const uint32_t b[2]){
    asm volatile("mma.sync.aligned.m16n8k8.row.col.f32.tf32.tf32.f32 "
        "{%0,%1,%2,%3}, {%4,%5,%6,%7}, {%8,%9}, {%0,%1,%2,%3};"
        : "+f"(d[0]), "+f"(d[1]), "+f"(d[2]), "+f"(d[3])
        : "r"(a[0]), "r"(a[1]), "r"(a[2]), "r"(a[3]), "r"(b[0]), "r"(b[1]));
}

// ---------------------------------------------------------------------------
// Kernel 1: projection GEMM -> Qhi/Qlo/Khi/Klo [b][n][32], Vt [b][c][n] (tf32)
// ---------------------------------------------------------------------------
__global__ void proj_kernel(const float* __restrict__ x,
                            const float* __restrict__ Wq, const float* __restrict__ bq,
                            const float* __restrict__ Wk, const float* __restrict__ bk,
                            const float* __restrict__ Wv, const float* __restrict__ bv)
{
    __shared__ float Ws[64*32];
    __shared__ float Xs[32*128];
    const int t = threadIdx.x, n0 = blockIdx.x*128, o0 = blockIdx.y*64, b = blockIdx.z;
    const int tr = t >> 5, tc = t & 31;

    unsigned long long acc[8][2];
    #pragma unroll
    for (int r = 0; r < 8; r++) { acc[r][0] = 0ull; acc[r][1] = 0ull; }

    for (int k0 = 0; k0 < 256; k0 += 32) {
        __syncthreads();
        #pragma unroll
        for (int it = 0; it < 2; it++) {
            int f = t + it*256, oo = f >> 3, c4 = f & 7, o = o0 + oo;
            const float* src = (o < 32) ? Wq + o*256 : (o < 64) ? Wk + (o-32)*256 : Wv + (o-64)*256;
            *(float4*)(Ws + oo*32 + c4*4) = *(const float4*)(src + k0 + c4*4);
        }
        #pragma unroll
        for (int it = 0; it < 4; it++) {
            int f = t + it*256, cc = f >> 5, n4 = f & 31;
            *(float4*)(Xs + cc*128 + n4*4) =
                *(const float4*)(x + ((size_t)b*Cc + k0 + cc)*Nn + n0 + n4*4);
        }
        __syncthreads();
        #pragma unroll 4
        for (int cc = 0; cc < 32; cc++) {
            float4 xv = *(const float4*)(Xs + cc*128 + tc*4);
            unsigned long long x0, x1;
            asm("mov.b64 %0, {%1,%2};" : "=l"(x0) : "f"(xv.x), "f"(xv.y));
            asm("mov.b64 %0, {%1,%2};" : "=l"(x1) : "f"(xv.z), "f"(xv.w));
            #pragma unroll
            for (int r = 0; r < 8; r++) {
                float w = Ws[(tr*8 + r)*32 + cc];
                unsigned long long w2;
                asm("mov.b64 %0, {%1,%1};" : "=l"(w2) : "f"(w));
                asm("fma.rn.f32x2 %0, %1, %2, %0;" : "+l"(acc[r][0]) : "l"(x0), "l"(w2));
                asm("fma.rn.f32x2 %0, %1, %2, %0;" : "+l"(acc[r][1]) : "l"(x1), "l"(w2));
            }
        }
    }
    #pragma unroll
    for (int r = 0; r < 8; r++) {
        int o = o0 + tr*8 + r, nb = n0 + tc*4;
        float f[4];
        asm("mov.b64 {%0,%1}, %2;" : "=f"(f[0]), "=f"(f[1]) : "l"(acc[r][0]));
        asm("mov.b64 {%0,%1}, %2;" : "=f"(f[2]), "=f"(f[3]) : "l"(acc[r][1]));
        if (o < 64) {
            int od = o & 31;
            float bsv = (o < 32) ? bq[od] : bk[od];
            float* hi = (o < 32) ? g_Qhi : g_Khi;
            float* lo = (o < 32) ? g_Qlo : g_Klo;
            #pragma unroll
            for (int i = 0; i < 4; i++) {
                float v = f[i] + bsv, h = tf32r(v);
                hi[((size_t)b*Nn + nb + i)*32 + od] = h;
                lo[((size_t)b*Nn + nb + i)*32 + od] = tf32r(v - h);
            }
        } else {
            int od = o - 64; float bsv = bv[od];
            float4 v = make_float4(tf32r(f[0]+bsv), tf32r(f[1]+bsv), tf32r(f[2]+bsv), tf32r(f[3]+bsv));
            *(float4*)(g_Vt + ((size_t)b*Cc + od)*Nn + nb) = v;
        }
    }
}

// ---------------------------------------------------------------------------
// Kernel 2: mma.sync tf32 flash attention + residual. grid (32, 4), 512 thr.
// S: warp = 16 rows x 32 keys (pair of warps covers 64 keys).
// PV: warp = 32 rows x 64 cols (4 col-quarters).
// smem float offsets:
#define KHI_O 0                       // 64*36
#define KLO_O 2304
#define V_O   4608                    // 2 buffers of 256*68
#define P_O   39424                   // 128*76
#define LS_O  49152                   // 256 (row x keyhalf)
#define SMF   49408                   // 197632 B
// Os (final transpose) reuses V region: 256*132 floats
// ---------------------------------------------------------------------------
__global__ void __launch_bounds__(512, 1)
attn_kernel(const float* __restrict__ x, float* __restrict__ out)
{
    extern __shared__ float sm[];
    const int t = threadIdx.x, w = t >> 5, lane = t & 31;
    const int g = lane >> 2, m = lane & 3;
    const int b = blockIdx.y, QI0 = blockIdx.x * 128;
    const int rg16 = w >> 1, kh = w & 1;          // S: rows rg16*16, keys kh*32
    const int rp = (w & 3) * 32, cq = (w >> 2) * 64;  // PV rows/cols
    const float* gV = g_Vt + (size_t)b*Cc*Nn;

    // Q fragments (tile-invariant, registers)
    uint32_t qh[4][4], ql[4][4];
    #pragma unroll
    for (int ks = 0; ks < 4; ks++)
        #pragma unroll
        for (int i = 0; i < 4; i++) {
            size_t gi = ((size_t)b*Nn + QI0 + rg16*16 + g + (i&1)*8)*32 + ks*8 + m + (i>>1)*4;
            qh[ks][i] = __float_as_uint(g_Qhi[gi]);
            ql[ks][i] = __float_as_uint(g_Qlo[gi]);
        }

    float o[2][8][4];
    #pragma unroll
    for (int mt = 0; mt < 2; mt++)
        #pragma unroll
        for (int nb = 0; nb < 8; nb++)
            #pragma unroll
            for (int i = 0; i < 4; i++) o[mt][nb][i] = 0.f;
    float lsum0 = 0.f, lsum1 = 0.f;

    // prologue: stage K(0), V(0)
    {
        int j = t >> 3, d4 = t & 7;
        size_t gi = ((size_t)b*Nn + j)*32 + d4*4;
        *(float4*)(sm + KHI_O + j*36 + d4*4) = *(const float4*)(g_Khi + gi);
        *(float4*)(sm + KLO_O + j*36 + d4*4) = *(const float4*)(g_Klo + gi);
    }
    #pragma unroll
    for (int it = 0; it < 8; it++) {
        int f = t + it*512, c = f >> 4, j4 = f & 15;
        *(float4*)(sm + V_O + c*68 + j4*4) = *(const float4*)(gV + (size_t)c*Nn + j4*4);
    }
    __syncthreads();

    for (int tt = 0; tt < 64; tt++) {
        const float* Vb = sm + V_O + (tt & 1)*17408;
        // ---- S stage: 16 rows x 32 keys, per-nb exp ----
        #pragma unroll
        for (int nb = 0; nb < 4; nb++) {
            float s4[4] = {0.f, 0.f, 0.f, 0.f};
            #pragma unroll
            for (int ks = 0; ks < 4; ks++) {
                const float* kr = sm + KHI_O + (kh*32 + nb*8 + g)*36 + ks*8 + m;
                uint32_t bh[2] = { __float_as_uint(kr[0]), __float_as_uint(kr[4]) };
                const float* kl = sm + KLO_O + (kh*32 + nb*8 + g)*36 + ks*8 + m;
                uint32_t bl[2] = { __float_as_uint(kl[0]), __float_as_uint(kl[4]) };
                mma8(s4, qh[ks], bh);
                mma8(s4, qh[ks], bl);
                mma8(s4, ql[ks], bh);
            }
            float p0 = __expf(s4[0]), p1 = __expf(s4[1]);
            float p2 = __expf(s4[2]), p3 = __expf(s4[3]);
            lsum0 += p0 + p1;  lsum1 += p2 + p3;
            int col = kh*32 + nb*8 + 2*m;
            *(float2*)(sm + P_O + (rg16*16 + g)*76 + col)     = make_float2(tf32r(p0), tf32r(p1));
            *(float2*)(sm + P_O + (rg16*16 + g + 8)*76 + col) = make_float2(tf32r(p2), tf32r(p3));
        }
        __syncthreads();   // P complete; V(tt) ready; K consumed

        // ---- PV stage: O[rp..rp+31][cq..cq+63] += P x V ----
        #pragma unroll 2
        for (int ks = 0; ks < 8; ks++) {
            uint32_t a0[4], a1[4];
            #pragma unroll
            for (int i = 0; i < 4; i++) {
                a0[i] = __float_as_uint(sm[P_O + (rp + g + (i&1)*8)*76      + ks*8 + m + (i>>1)*4]);
                a1[i] = __float_as_uint(sm[P_O + (rp + 16 + g + (i&1)*8)*76 + ks*8 + m + (i>>1)*4]);
            }
            #pragma unroll
            for (int nb = 0; nb < 8; nb++) {
                const float* vr = Vb + (cq + nb*8 + g)*68 + ks*8 + m;
                uint32_t bb[2] = { __float_as_uint(vr[0]), __float_as_uint(vr[4]) };
                mma8(o[0][nb], a0, bb);
                mma8(o[1][nb], a1, bb);
            }
        }
        // ---- stage K,V for tt+1 ----
        if (tt < 63) {
            int j0 = (tt + 1) * 64;
            float* Vn = sm + V_O + ((tt + 1) & 1)*17408;
            {
                int j = t >> 3, d4 = t & 7;
                size_t gi = ((size_t)b*Nn + j0 + j)*32 + d4*4;
                *(float4*)(sm + KHI_O + j*36 + d4*4) = *(const float4*)(g_Khi + gi);
                *(float4*)(sm + KLO_O + j*36 + d4*4) = *(const float4*)(g_Klo + gi);
            }
            #pragma unroll
            for (int it = 0; it < 8; it++) {
                int f = t + it*512, c = f >> 4, j4 = f & 15;
                *(float4*)(Vn + c*68 + j4*4) = *(const float4*)(gV + (size_t)c*Nn + j0 + j4*4);
            }
        }
        __syncthreads();   // stage done + all PV done (P(t+1) safe to write)
    }

    // ---- row sums: reduce over m, combine key halves via smem ----
    lsum0 += __shfl_xor_sync(0xffffffffu, lsum0, 1);
    lsum0 += __shfl_xor_sync(0xffffffffu, lsum0, 2);
    lsum1 += __shfl_xor_sync(0xffffffffu, lsum1, 1);
    lsum1 += __shfl_xor_sync(0xffffffffu, lsum1, 2);
    if (m == 0) {
        sm[LS_O + (rg16*16 + g)*2 + kh]     = lsum0;
        sm[LS_O + (rg16*16 + g + 8)*2 + kh] = lsum1;
    }
    __syncthreads();       // ls ready; all PV done -> V region reusable as Os

    // ---- normalize + transpose through smem Os[c][r] (stride 132) ----
    float* Os = sm + V_O;
    #pragma unroll
    for (int mt = 0; mt < 2; mt++) {
        int r0 = rp + mt*16 + g;
        float iv0 = 1.0f / (sm[LS_O + r0*2]       + sm[LS_O + r0*2 + 1]);
        float iv1 = 1.0f / (sm[LS_O + (r0+8)*2]   + sm[LS_O + (r0+8)*2 + 1]);
        #pragma unroll
        for (int nb = 0; nb < 8; nb++) {
            int c = cq + nb*8 + 2*m;
            Os[(c    )*132 + r0    ] = o[mt][nb][0] * iv0;
            Os[(c + 1)*132 + r0    ] = o[mt][nb][1] * iv0;
            Os[(c    )*132 + r0 + 8] = o[mt][nb][2] * iv1;
            Os[(c + 1)*132 + r0 + 8] = o[mt][nb][3] * iv1;
        }
    }
    __syncthreads();

    // ---- coalesced residual + store: out[b][c][QI0+r] ----
    const float* xb = x   + (size_t)b*Cc*Nn + QI0;
    float*       ob = out + (size_t)b*Cc*Nn + QI0;
    const int r4 = (t & 31) * 4, c0 = t >> 5;
    #pragma unroll 4
    for (int k = 0; k < 16; k++) {
        int c = k*16 + c0;
        float4 ov = *(const float4*)(Os + c*132 + r4);
        float4 xv = *(const float4*)(xb + (size_t)c*Nn + r4);
        ov.x += xv.x; ov.y += xv.y; ov.z += xv.z; ov.w += xv.w;
        *(float4*)(ob + (size_t)c*Nn + r4) = ov;
    }
}

// ---------------------------------------------------------------------------
extern "C" void kernel_launch(void* const* d_in, const int* in_sizes, int n_in,
                              void* d_out, int out_size)
{
    const float* x  = (const float*)d_in[0];
    const float* Wq = (const float*)d_in[1];
    const float* bq = (const float*)d_in[2];
    const float* Wk = (const float*)d_in[3];
    const float* bk = (const float*)d_in[4];
    const float* Wv = (const float*)d_in[5];
    const float* bv = (const float*)d_in[6];
    float* out = (float*)d_out;

    cudaFuncSetAttribute(attn_kernel, cudaFuncAttributeMaxDynamicSharedMemorySize, SMF*4);
    proj_kernel<<<dim3(Nn/128, 5, Bc), 256>>>(x, Wq, bq, Wk, bk, Wv, bv);
    attn_kernel<<<dim3(Nn/128, Bc), 512, SMF*4>>>(x, out);
}

// round 14
// speedup vs baseline: 1.3417x; 1.3417x over previous
#include <cuda_runtime.h>
#include <cuda_bf16.h>
#include <cstdint>

#define Bc 4
#define Cc 256
#define Nn 4096

__device__ __nv_bfloat16 g_Qbh[(size_t)Bc*Nn*32];
__device__ __nv_bfloat16 g_Qbl[(size_t)Bc*Nn*32];
__device__ __nv_bfloat16 g_Kbh[(size_t)Bc*Nn*32];
__device__ __nv_bfloat16 g_Kbl[(size_t)Bc*Nn*32];
__device__ float g_Vt[(size_t)Bc*Cc*Nn];   // [b][c][n], tf32-rounded

__device__ __forceinline__ float tf32r(float x){
    uint32_t u; asm("cvt.rna.tf32.f32 %0, %1;" : "=r"(u) : "f"(x));
    return __uint_as_float(u);
}
// tf32 m16n8k8 (PV)
__device__ __forceinline__ void mma8(float d[4], const uint32_t a[4], const uint32_t b[2]){
    asm volatile("mma.sync.aligned.m16n8k8.row.col.f32.tf32.tf32.f32 "
        "{%0,%1,%2,%3}, {%4,%5,%6,%7}, {%8,%9}, {%0,%1,%2,%3};"
        : "+f"(d[0]), "+f"(d[1]), "+f"(d[2]), "+f"(d[3])
        : "r"(a[0]), "r"(a[1]), "r"(a[2]), "r"(a[3]), "r"(b[0]), "r"(b[1]));
}
// bf16 m16n8k16 (S)
__device__ __forceinline__ void mma16(float d[4], const uint32_t a[4], const uint32_t b[2]){
    asm volatile("mma.sync.aligned.m16n8k16.row.col.f32.bf16.bf16.f32 "
        "{%0,%1,%2,%3}, {%4,%5,%6,%7}, {%8,%9}, {%0,%1,%2,%3};"
        : "+f"(d[0]), "+f"(d[1]), "+f"(d[2]), "+f"(d[3])
        : "r"(a[0]), "r"(a[1]), "r"(a[2]), "r"(a[3]), "r"(b[0]), "r"(b[1]));
}

// ---------------------------------------------------------------------------
// Kernel 1: projection GEMM -> Q/K bf16 hi+lo [b][n][32], Vt [b][c][n] (tf32)
// ---------------------------------------------------------------------------
__global__ void proj_kernel(const float* __restrict__ x,
                            const float* __restrict__ Wq, const float* __restrict__ bq,
                            const float* __restrict__ Wk, const float* __restrict__ bk,
                            const float* __restrict__ Wv, const float* __restrict__ bv)
{
    __shared__ float Ws[64*32];
    __shared__ float Xs[32*128];
    const int t = threadIdx.x, n0 = blockIdx.x*128, o0 = blockIdx.y*64, b = blockIdx.z;
    const int tr = t >> 5, tc = t & 31;

    unsigned long long acc[8][2];
    #pragma unroll
    for (int r = 0; r < 8; r++) { acc[r][0] = 0ull; acc[r][1] = 0ull; }

    for (int k0 = 0; k0 < 256; k0 += 32) {
        __syncthreads();
        #pragma unroll
        for (int it = 0; it < 2; it++) {
            int f = t + it*256, oo = f >> 3, c4 = f & 7, o = o0 + oo;
            const float* src = (o < 32) ? Wq + o*256 : (o < 64) ? Wk + (o-32)*256 : Wv + (o-64)*256;
            *(float4*)(Ws + oo*32 + c4*4) = *(const float4*)(src + k0 + c4*4);
        }
        #pragma unroll
        for (int it = 0; it < 4; it++) {
            int f = t + it*256, cc = f >> 5, n4 = f & 31;
            *(float4*)(Xs + cc*128 + n4*4) =
                *(const float4*)(x + ((size_t)b*Cc + k0 + cc)*Nn + n0 + n4*4);
        }
        __syncthreads();
        #pragma unroll 4
        for (int cc = 0; cc < 32; cc++) {
            float4 xv = *(const float4*)(Xs + cc*128 + tc*4);
            unsigned long long x0, x1;
            asm("mov.b64 %0, {%1,%2};" : "=l"(x0) : "f"(xv.x), "f"(xv.y));
            asm("mov.b64 %0, {%1,%2};" : "=l"(x1) : "f"(xv.z), "f"(xv.w));
            #pragma unroll
            for (int r = 0; r < 8; r++) {
                float w = Ws[(tr*8 + r)*32 + cc];
                unsigned long long w2;
                asm("mov.b64 %0, {%1,%1};" : "=l"(w2) : "f"(w));
                asm("fma.rn.f32x2 %0, %1, %2, %0;" : "+l"(acc[r][0]) : "l"(x0), "l"(w2));
                asm("fma.rn.f32x2 %0, %1, %2, %0;" : "+l"(acc[r][1]) : "l"(x1), "l"(w2));
            }
        }
    }
    #pragma unroll
    for (int r = 0; r < 8; r++) {
        int o = o0 + tr*8 + r, nb = n0 + tc*4;
        float f[4];
        asm("mov.b64 {%0,%1}, %2;" : "=f"(f[0]), "=f"(f[1]) : "l"(acc[r][0]));
        asm("mov.b64 {%0,%1}, %2;" : "=f"(f[2]), "=f"(f[3]) : "l"(acc[r][1]));
        if (o < 64) {
            int od = o & 31;
            float bsv = (o < 32) ? bq[od] : bk[od];
            __nv_bfloat16* hi = (o < 32) ? g_Qbh : g_Kbh;
            __nv_bfloat16* lo = (o < 32) ? g_Qbl : g_Kbl;
            #pragma unroll
            for (int i = 0; i < 4; i++) {
                float v = f[i] + bsv;
                __nv_bfloat16 h = __float2bfloat16(v);
                hi[((size_t)b*Nn + nb + i)*32 + od] = h;
                lo[((size_t)b*Nn + nb + i)*32 + od] = __float2bfloat16(v - __bfloat162float(h));
            }
        } else {
            int od = o - 64; float bsv = bv[od];
            float4 v = make_float4(tf32r(f[0]+bsv), tf32r(f[1]+bsv), tf32r(f[2]+bsv), tf32r(f[3]+bsv));
            *(float4*)(g_Vt + ((size_t)b*Cc + od)*Nn + nb) = v;
        }
    }
}

// ---------------------------------------------------------------------------
// Kernel 2: flash attention. grid (32, 4), 256 threads.
// S: bf16 m16n8k16, 3-pass hi/lo split; warp = 16 rows x 64 keys.
// PV: tf32 m16n8k8; warp = 64 rows x 64 cols (2x4 warp grid).
// smem (float offsets):
#define KH_O 0                        // 64 rows x 20 u32 (bf16x2)
#define KL_O 1280
#define V_O  2560                     // 2 buffers of 256*68
#define P_O  37376                    // 128*76
#define LS_O 47104                    // 128
#define SMF  47232                    // 188928 B
// Os (final transpose) reuses V region: 256*132 floats
// ---------------------------------------------------------------------------
__global__ void __launch_bounds__(256, 1)
attn_kernel(const float* __restrict__ x, float* __restrict__ out)
{
    extern __shared__ float sm[];
    uint32_t* smu = (uint32_t*)sm;
    const int t = threadIdx.x, w = t >> 5, lane = t & 31;
    const int g = lane >> 2, m = lane & 3;
    const int b = blockIdx.y, QI0 = blockIdx.x * 128;
    const int rs = w * 16;                           // S rows
    const int rowg = (w & 1) * 64, colg = (w >> 1) * 64;  // PV tile
    const float* gV = g_Vt + (size_t)b*Cc*Nn;

    // Q bf16 fragments (tile-invariant): qh/ql[ks][i], ks = d16-block
    uint32_t qh[2][4], ql[2][4];
    #pragma unroll
    for (int ks = 0; ks < 2; ks++)
        #pragma unroll
        for (int i = 0; i < 4; i++) {
            size_t row = (size_t)b*Nn + QI0 + rs + g + (i&1)*8;
            int d = ks*16 + 2*m + (i>>1)*8;
            qh[ks][i] = *(const uint32_t*)(g_Qbh + row*32 + d);
            ql[ks][i] = *(const uint32_t*)(g_Qbl + row*32 + d);
        }

    float o[4][8][4];
    #pragma unroll
    for (int rb = 0; rb < 4; rb++)
        #pragma unroll
        for (int cb = 0; cb < 8; cb++)
            #pragma unroll
            for (int i = 0; i < 4; i++) o[rb][cb][i] = 0.f;
    float lsum0 = 0.f, lsum1 = 0.f;

    // prologue: stage K(0) (bf16 hi/lo as u32 rows of 16 + pad4), V(0)
    {
        int j = t >> 2, q4 = t & 3;
        const uint4* sh = (const uint4*)(g_Kbh + ((size_t)b*Nn + j)*32);
        const uint4* sl = (const uint4*)(g_Kbl + ((size_t)b*Nn + j)*32);
        *(uint4*)(smu + KH_O + j*20 + q4*4) = sh[q4];
        *(uint4*)(smu + KL_O + j*20 + q4*4) = sl[q4];
    }
    #pragma unroll
    for (int it = 0; it < 16; it++) {
        int f = t + it*256, c = f >> 4, j4 = f & 15;
        *(float4*)(sm + V_O + c*68 + j4*4) = *(const float4*)(gV + (size_t)c*Nn + j4*4);
    }
    __syncthreads();

    for (int tt = 0; tt < 64; tt++) {
        const float* Vb = sm + V_O + (tt & 1)*17408;
        // ---- S stage: 16 rows x 64 keys, bf16 3-pass ----
        float s[8][4];
        #pragma unroll
        for (int nb = 0; nb < 8; nb++) {
            #pragma unroll
            for (int i = 0; i < 4; i++) s[nb][i] = 0.f;
            #pragma unroll
            for (int ks = 0; ks < 2; ks++) {
                const uint32_t* kh = smu + KH_O + (nb*8 + g)*20 + ks*8 + m;
                const uint32_t* kl = smu + KL_O + (nb*8 + g)*20 + ks*8 + m;
                uint32_t bh[2] = { kh[0], kh[4] };
                uint32_t bl[2] = { kl[0], kl[4] };
                mma16(s[nb], qh[ks], bh);
                mma16(s[nb], qh[ks], bl);
                mma16(s[nb], ql[ks], bh);
            }
        }
        // ---- exp (no max: |s| < 45) + P store (tf32) + row sums ----
        #pragma unroll
        for (int nb = 0; nb < 8; nb++) {
            float p0 = __expf(s[nb][0]), p1 = __expf(s[nb][1]);
            float p2 = __expf(s[nb][2]), p3 = __expf(s[nb][3]);
            lsum0 += p0 + p1;  lsum1 += p2 + p3;
            float* Pr0 = sm + P_O + (rs + g)*76 + nb*8 + 2*m;
            float* Pr1 = sm + P_O + (rs + g + 8)*76 + nb*8 + 2*m;
            Pr0[0] = tf32r(p0); Pr0[1] = tf32r(p1);
            Pr1[0] = tf32r(p2); Pr1[1] = tf32r(p3);
        }
        __syncthreads();   // P complete; V(tt) ready; K consumed

        // ---- PV stage: O[rowg..+63][colg..+63] += P x V (tf32) ----
        #pragma unroll 2
        for (int ks = 0; ks < 8; ks++) {
            uint32_t a[4][4];
            #pragma unroll
            for (int rb = 0; rb < 4; rb++)
                #pragma unroll
                for (int i = 0; i < 4; i++)
                    a[rb][i] = __float_as_uint(
                        sm[P_O + (rowg + rb*16 + g + (i&1)*8)*76 + ks*8 + m + (i>>1)*4]);
            #pragma unroll
            for (int cb = 0; cb < 8; cb++) {
                const float* vr = Vb + (colg + cb*8 + g)*68 + ks*8 + m;
                uint32_t bb[2] = { __float_as_uint(vr[0]), __float_as_uint(vr[4]) };
                #pragma unroll
                for (int rb = 0; rb < 4; rb++) mma8(o[rb][cb], a[rb], bb);
            }
        }
        // ---- stage K,V for tt+1 ----
        if (tt < 63) {
            int j0 = (tt + 1) * 64;
            float* Vn = sm + V_O + ((tt + 1) & 1)*17408;
            {
                int j = t >> 2, q4 = t & 3;
                const uint4* sh = (const uint4*)(g_Kbh + ((size_t)b*Nn + j0 + j)*32);
                const uint4* sl = (const uint4*)(g_Kbl + ((size_t)b*Nn + j0 + j)*32);
                *(uint4*)(smu + KH_O + j*20 + q4*4) = sh[q4];
                *(uint4*)(smu + KL_O + j*20 + q4*4) = sl[q4];
            }
            #pragma unroll
            for (int it = 0; it < 16; it++) {
                int f = t + it*256, c = f >> 4, j4 = f & 15;
                *(float4*)(Vn + c*68 + j4*4) = *(const float4*)(gV + (size_t)c*Nn + j0 + j4*4);
            }
        }
        __syncthreads();   // stage done + all PV done (P(t+1) safe)
    }

    // ---- row sums -> smem ----
    lsum0 += __shfl_xor_sync(0xffffffffu, lsum0, 1);
    lsum0 += __shfl_xor_sync(0xffffffffu, lsum0, 2);
    lsum1 += __shfl_xor_sync(0xffffffffu, lsum1, 1);
    lsum1 += __shfl_xor_sync(0xffffffffu, lsum1, 2);
    if (m == 0) { sm[LS_O + rs + g] = lsum0; sm[LS_O + rs + g + 8] = lsum1; }
    __syncthreads();       // ls ready; V region reusable as Os

    // ---- normalize + transpose through smem Os[c][r] (stride 132) ----
    float* Os = sm + V_O;
    #pragma unroll
    for (int rb = 0; rb < 4; rb++) {
        int r0 = rowg + rb*16 + g;
        float iv0 = 1.0f / sm[LS_O + r0];
        float iv1 = 1.0f / sm[LS_O + r0 + 8];
        #pragma unroll
        for (int cb = 0; cb < 8; cb++) {
            int c = colg + cb*8 + 2*m;
            Os[(c    )*132 + r0    ] = o[rb][cb][0] * iv0;
            Os[(c + 1)*132 + r0    ] = o[rb][cb][1] * iv0;
            Os[(c    )*132 + r0 + 8] = o[rb][cb][2] * iv1;
            Os[(c + 1)*132 + r0 + 8] = o[rb][cb][3] * iv1;
        }
    }
    __syncthreads();

    // ---- coalesced residual + store: out[b][c][QI0+r] ----
    const float* xb = x   + (size_t)b*Cc*Nn + QI0;
    float*       ob = out + (size_t)b*Cc*Nn + QI0;
    const int r4 = (t & 31) * 4, c0 = t >> 5;
    #pragma unroll 4
    for (int k = 0; k < 32; k++) {
        int c = k*8 + c0;
        float4 ov = *(const float4*)(Os + c*132 + r4);
        float4 xv = *(const float4*)(xb + (size_t)c*Nn + r4);
        ov.x += xv.x; ov.y += xv.y; ov.z += xv.z; ov.w += xv.w;
        *(float4*)(ob + (size_t)c*Nn + r4) = ov;
    }
}

// ---------------------------------------------------------------------------
extern "C" void kernel_launch(void* const* d_in, const int* in_sizes, int n_in,
                              void* d_out, int out_size)
{
    const float* x  = (const float*)d_in[0];
    const float* Wq = (const float*)d_in[1];
    const float* bq = (const float*)d_in[2];
    const float* Wk = (const float*)d_in[3];
    const float* bk = (const float*)d_in[4];
    const float* Wv = (const float*)d_in[5];
    const float* bv = (const float*)d_in[6];
    float* out = (float*)d_out;

    cudaFuncSetAttribute(attn_kernel, cudaFuncAttributeMaxDynamicSharedMemorySize, SMF*4);
    proj_kernel<<<dim3(Nn/128, 5, Bc), 256>>>(x, Wq, bq, Wk, bk, Wv, bv);
    attn_kernel<<<dim3(Nn/128, Bc), 256, SMF*4>>>(x, out);
}

// round 16
// speedup vs baseline: 1.8005x; 1.3420x over previous
#include <cuda_runtime.h>
#include <cuda_bf16.h>
#include <cuda_fp16.h>
#include <cstdint>

#define Bc 4
#define Cc 256
#define Nn 4096

__device__ __nv_bfloat16 g_Qbh[(size_t)Bc*Nn*32];
__device__ __nv_bfloat16 g_Qbl[(size_t)Bc*Nn*32];
__device__ __nv_bfloat16 g_Kbh[(size_t)Bc*Nn*32];
__device__ __nv_bfloat16 g_Kbl[(size_t)Bc*Nn*32];
__device__ __half g_Vh[(size_t)Bc*Cc*Nn];   // [b][c][n], fp16

// bf16 m16n8k16 (S)
__device__ __forceinline__ void mma16b(float d[4], const uint32_t a[4], const uint32_t b[2]){
    asm volatile("mma.sync.aligned.m16n8k16.row.col.f32.bf16.bf16.f32 "
        "{%0,%1,%2,%3}, {%4,%5,%6,%7}, {%8,%9}, {%0,%1,%2,%3};"
        : "+f"(d[0]), "+f"(d[1]), "+f"(d[2]), "+f"(d[3])
        : "r"(a[0]), "r"(a[1]), "r"(a[2]), "r"(a[3]), "r"(b[0]), "r"(b[1]));
}
// fp16 m16n8k16 (PV)
__device__ __forceinline__ void mma16f(float d[4], const uint32_t a[4], const uint32_t b[2]){
    asm volatile("mma.sync.aligned.m16n8k16.row.col.f32.f16.f16.f32 "
        "{%0,%1,%2,%3}, {%4,%5,%6,%7}, {%8,%9}, {%0,%1,%2,%3};"
        : "+f"(d[0]), "+f"(d[1]), "+f"(d[2]), "+f"(d[3])
        : "r"(a[0]), "r"(a[1]), "r"(a[2]), "r"(a[3]), "r"(b[0]), "r"(b[1]));
}

// ---------------------------------------------------------------------------
// Kernel 1: projection GEMM -> Q/K bf16 hi+lo [b][n][32], Vh [b][c][n] (fp16)
// ---------------------------------------------------------------------------
__global__ void proj_kernel(const float* __restrict__ x,
                            const float* __restrict__ Wq, const float* __restrict__ bq,
                            const float* __restrict__ Wk, const float* __restrict__ bk,
                            const float* __restrict__ Wv, const float* __restrict__ bv)
{
    __shared__ float Ws[64*32];
    __shared__ float Xs[32*128];
    const int t = threadIdx.x, n0 = blockIdx.x*128, o0 = blockIdx.y*64, b = blockIdx.z;
    const int tr = t >> 5, tc = t & 31;

    unsigned long long acc[8][2];
    #pragma unroll
    for (int r = 0; r < 8; r++) { acc[r][0] = 0ull; acc[r][1] = 0ull; }

    for (int k0 = 0; k0 < 256; k0 += 32) {
        __syncthreads();
        #pragma unroll
        for (int it = 0; it < 2; it++) {
            int f = t + it*256, oo = f >> 3, c4 = f & 7, o = o0 + oo;
            const float* src = (o < 32) ? Wq + o*256 : (o < 64) ? Wk + (o-32)*256 : Wv + (o-64)*256;
            *(float4*)(Ws + oo*32 + c4*4) = *(const float4*)(src + k0 + c4*4);
        }
        #pragma unroll
        for (int it = 0; it < 4; it++) {
            int f = t + it*256, cc = f >> 5, n4 = f & 31;
            *(float4*)(Xs + cc*128 + n4*4) =
                *(const float4*)(x + ((size_t)b*Cc + k0 + cc)*Nn + n0 + n4*4);
        }
        __syncthreads();
        #pragma unroll 4
        for (int cc = 0; cc < 32; cc++) {
            float4 xv = *(const float4*)(Xs + cc*128 + tc*4);
            unsigned long long x0, x1;
            asm("mov.b64 %0, {%1,%2};" : "=l"(x0) : "f"(xv.x), "f"(xv.y));
            asm("mov.b64 %0, {%1,%2};" : "=l"(x1) : "f"(xv.z), "f"(xv.w));
            #pragma unroll
            for (int r = 0; r < 8; r++) {
                float w = Ws[(tr*8 + r)*32 + cc];
                unsigned long long w2;
                asm("mov.b64 %0, {%1,%1};" : "=l"(w2) : "f"(w));
                asm("fma.rn.f32x2 %0, %1, %2, %0;" : "+l"(acc[r][0]) : "l"(x0), "l"(w2));
                asm("fma.rn.f32x2 %0, %1, %2, %0;" : "+l"(acc[r][1]) : "l"(x1), "l"(w2));
            }
        }
    }
    #pragma unroll
    for (int r = 0; r < 8; r++) {
        int o = o0 + tr*8 + r, nb = n0 + tc*4;
        float f[4];
        asm("mov.b64 {%0,%1}, %2;" : "=f"(f[0]), "=f"(f[1]) : "l"(acc[r][0]));
        asm("mov.b64 {%0,%1}, %2;" : "=f"(f[2]), "=f"(f[3]) : "l"(acc[r][1]));
        if (o < 64) {
            int od = o & 31;
            float bsv = (o < 32) ? bq[od] : bk[od];
            __nv_bfloat16* hi = (o < 32) ? g_Qbh : g_Kbh;
            __nv_bfloat16* lo = (o < 32) ? g_Qbl : g_Kbl;
            #pragma unroll
            for (int i = 0; i < 4; i++) {
                float v = f[i] + bsv;
                __nv_bfloat16 h = __float2bfloat16(v);
                hi[((size_t)b*Nn + nb + i)*32 + od] = h;
                lo[((size_t)b*Nn + nb + i)*32 + od] = __float2bfloat16(v - __bfloat162float(h));
            }
        } else {
            int od = o - 64; float bsv = bv[od];
            __half2 h0 = __floats2half2_rn(f[0]+bsv, f[1]+bsv);
            __half2 h1 = __floats2half2_rn(f[2]+bsv, f[3]+bsv);
            uint2 u;
            u.x = *(uint32_t*)&h0;  u.y = *(uint32_t*)&h1;
            *(uint2*)(g_Vh + ((size_t)b*Cc + od)*Nn + nb) = u;
        }
    }
}

// ---------------------------------------------------------------------------
// Kernel 2: flash attention (online softmax). grid (32, 4), 256 threads.
// S: bf16 m16n8k16 3-pass; warp = 16 rows x 64 keys.
// PV: fp16 m16n8k16; warp = 64 rows x 64 cols; O rescaled by SCS[row] per tile.
// smem byte layout:
#define KH_B   0          // 64 x 20 u32 (bf16x2)      5120 B
#define KL_B   5120       //                           5120 B
#define V_B    10240      // 2 bufs: 256 rows x 36 u32 (36864 B each)
#define P_B    83968      // 128 rows x 36 u32 (half2) 18432 B
#define LS_B   102400     // 128 f32
#define SCS_B  102912     // 128 f32
#define SM_BYTES 103424
// Os overlay (epilogue): f32 at byte 0, 128 ch x 132 (2 rounds)
// ---------------------------------------------------------------------------
__global__ void __launch_bounds__(256, 1)
attn_kernel(const float* __restrict__ x, float* __restrict__ out)
{
    extern __shared__ char smc[];
    uint32_t* smu = (uint32_t*)smc;                 // K region (u32 view)
    uint32_t* P32 = (uint32_t*)(smc + P_B);
    float*    LS  = (float*)(smc + LS_B);
    float*    SCS = (float*)(smc + SCS_B);
    const int t = threadIdx.x, w = t >> 5, lane = t & 31;
    const int g = lane >> 2, m = lane & 3;
    const int b = blockIdx.y, QI0 = blockIdx.x * 128;
    const int rs = w * 16;                          // S rows
    const int rowg = (w & 1) * 64, colg = (w >> 1) * 64;  // PV tile
    const __half* gV = g_Vh + (size_t)b*Cc*Nn;

    // Q bf16 fragments (tile-invariant)
    uint32_t qh[2][4], ql[2][4];
    #pragma unroll
    for (int ks = 0; ks < 2; ks++)
        #pragma unroll
        for (int i = 0; i < 4; i++) {
            size_t row = (size_t)b*Nn + QI0 + rs + g + (i&1)*8;
            int d = ks*16 + 2*m + (i>>1)*8;
            qh[ks][i] = *(const uint32_t*)(g_Qbh + row*32 + d);
            ql[ks][i] = *(const uint32_t*)(g_Qbl + row*32 + d);
        }

    float o[4][8][4];
    #pragma unroll
    for (int rb = 0; rb < 4; rb++)
        #pragma unroll
        for (int cb = 0; cb < 8; cb++)
            #pragma unroll
            for (int i = 0; i < 4; i++) o[rb][cb][i] = 0.f;
    float lsum0 = 0.f, lsum1 = 0.f;
    float m0 = -1e30f, m1 = -1e30f;

    // prologue: stage K(0), V(0)
    {
        int j = t >> 2, q4 = t & 3;
        const uint4* sh = (const uint4*)(g_Kbh + ((size_t)b*Nn + j)*32);
        const uint4* sl = (const uint4*)(g_Kbl + ((size_t)b*Nn + j)*32);
        *(uint4*)(smu + j*20 + q4*4)        = sh[q4];
        *(uint4*)(smu + 1280 + j*20 + q4*4) = sl[q4];
    }
    {
        uint32_t* V0 = (uint32_t*)(smc + V_B);
        #pragma unroll
        for (int it = 0; it < 8; it++) {
            int f = t + it*256, c = f >> 3, ch = f & 7;
            uint4 v = *(const uint4*)(gV + (size_t)c*Nn + ch*8);
            *(uint4*)(V0 + c*36 + ch*4) = v;
        }
    }
    __syncthreads();

    for (int tt = 0; tt < 64; tt++) {
        uint32_t* V32 = (uint32_t*)(smc + V_B + (tt & 1)*36864);
        // ---- S stage: 16 rows x 64 keys, bf16 3-pass ----
        float s[8][4];
        #pragma unroll
        for (int nb = 0; nb < 8; nb++) {
            #pragma unroll
            for (int i = 0; i < 4; i++) s[nb][i] = 0.f;
            #pragma unroll
            for (int ks = 0; ks < 2; ks++) {
                const uint32_t* kh = smu + (nb*8 + g)*20 + ks*8 + m;
                const uint32_t* kl = smu + 1280 + (nb*8 + g)*20 + ks*8 + m;
                uint32_t bh[2] = { kh[0], kh[4] };
                uint32_t bl[2] = { kl[0], kl[4] };
                mma16b(s[nb], qh[ks], bh);
                mma16b(s[nb], qh[ks], bl);
                mma16b(s[nb], ql[ks], bh);
            }
        }
        // ---- online softmax: per-row max, rescale, fp16 P ----
        float t0 = -1e30f, t1 = -1e30f;
        #pragma unroll
        for (int nb = 0; nb < 8; nb++) {
            t0 = fmaxf(t0, fmaxf(s[nb][0], s[nb][1]));
            t1 = fmaxf(t1, fmaxf(s[nb][2], s[nb][3]));
        }
        t0 = fmaxf(t0, __shfl_xor_sync(0xffffffffu, t0, 1));
        t0 = fmaxf(t0, __shfl_xor_sync(0xffffffffu, t0, 2));
        t1 = fmaxf(t1, __shfl_xor_sync(0xffffffffu, t1, 1));
        t1 = fmaxf(t1, __shfl_xor_sync(0xffffffffu, t1, 2));
        float mn0 = fmaxf(m0, t0), mn1 = fmaxf(m1, t1);
        float sc0 = __expf(m0 - mn0), sc1 = __expf(m1 - mn1);
        m0 = mn0; m1 = mn1;
        float ps0 = 0.f, ps1 = 0.f;
        #pragma unroll
        for (int nb = 0; nb < 8; nb++) {
            float p0 = __expf(s[nb][0] - mn0), p1 = __expf(s[nb][1] - mn0);
            float p2 = __expf(s[nb][2] - mn1), p3 = __expf(s[nb][3] - mn1);
            ps0 += p0 + p1;  ps1 += p2 + p3;
            __half2 h01 = __floats2half2_rn(p0, p1);
            __half2 h23 = __floats2half2_rn(p2, p3);
            P32[(rs + g)*36 + nb*4 + m]     = *(uint32_t*)&h01;
            P32[(rs + g + 8)*36 + nb*4 + m] = *(uint32_t*)&h23;
        }
        lsum0 = lsum0*sc0 + ps0;
        lsum1 = lsum1*sc1 + ps1;
        if (m == 0) { SCS[rs + g] = sc0; SCS[rs + g + 8] = sc1; }
        __syncthreads();   // P+SCS complete; V(tt) ready; K consumed

        // ---- PV stage: rescale O, then O += P x V (fp16 k16) ----
        #pragma unroll
        for (int rb = 0; rb < 4; rb++) {
            float sa = SCS[rowg + rb*16 + g];
            float sb = SCS[rowg + rb*16 + g + 8];
            #pragma unroll
            for (int cb = 0; cb < 8; cb++) {
                o[rb][cb][0] *= sa; o[rb][cb][1] *= sa;
                o[rb][cb][2] *= sb; o[rb][cb][3] *= sb;
            }
        }
        #pragma unroll
        for (int ks = 0; ks < 4; ks++) {
            uint32_t a[4][4];
            #pragma unroll
            for (int rb = 0; rb < 4; rb++) {
                int R0 = (rowg + rb*16 + g)*36 + ks*8 + m;
                int R1 = (rowg + rb*16 + g + 8)*36 + ks*8 + m;
                a[rb][0] = P32[R0];     a[rb][1] = P32[R1];
                a[rb][2] = P32[R0 + 4]; a[rb][3] = P32[R1 + 4];
            }
            #pragma unroll
            for (int cb = 0; cb < 8; cb++) {
                int C = (colg + cb*8 + g)*36 + ks*8 + m;
                uint32_t bb[2] = { V32[C], V32[C + 4] };
                #pragma unroll
                for (int rb = 0; rb < 4; rb++) mma16f(o[rb][cb], a[rb], bb);
            }
        }
        // ---- stage K,V for tt+1 ----
        if (tt < 63) {
            int j0 = (tt + 1) * 64;
            {
                int j = t >> 2, q4 = t & 3;
                const uint4* sh = (const uint4*)(g_Kbh + ((size_t)b*Nn + j0 + j)*32);
                const uint4* sl = (const uint4*)(g_Kbl + ((size_t)b*Nn + j0 + j)*32);
                *(uint4*)(smu + j*20 + q4*4)        = sh[q4];
                *(uint4*)(smu + 1280 + j*20 + q4*4) = sl[q4];
            }
            uint32_t* Vn = (uint32_t*)(smc + V_B + ((tt + 1) & 1)*36864);
            #pragma unroll
            for (int it = 0; it < 8; it++) {
                int f = t + it*256, c = f >> 3, ch = f & 7;
                uint4 v = *(const uint4*)(gV + (size_t)c*Nn + j0 + ch*8);
                *(uint4*)(Vn + c*36 + ch*4) = v;
            }
        }
        __syncthreads();   // stage done + all PV done (P/SCS(t+1) safe)
    }

    // ---- row sums -> smem ----
    lsum0 += __shfl_xor_sync(0xffffffffu, lsum0, 1);
    lsum0 += __shfl_xor_sync(0xffffffffu, lsum0, 2);
    lsum1 += __shfl_xor_sync(0xffffffffu, lsum1, 1);
    lsum1 += __shfl_xor_sync(0xffffffffu, lsum1, 2);
    if (m == 0) { LS[rs + g] = lsum0; LS[rs + g + 8] = lsum1; }

    // ---- epilogue: 2 channel-rounds through Os[cloc][r] (f32, stride 132) ----
    float* Os = (float*)smc;
    const float* xb = x   + (size_t)b*Cc*Nn + QI0;
    float*       ob = out + (size_t)b*Cc*Nn + QI0;
    const int r4 = (t & 31) * 4, c0 = t >> 5;
    #pragma unroll
    for (int h2 = 0; h2 < 2; h2++) {
        __syncthreads();   // LS ready (rnd0) / prior stores read (rnd1)
        if ((colg >> 7) == h2) {
            #pragma unroll
            for (int rb = 0; rb < 4; rb++) {
                int r0 = rowg + rb*16 + g;
                float iv0 = 1.0f / LS[r0];
                float iv1 = 1.0f / LS[r0 + 8];
                #pragma unroll
                for (int cb = 0; cb < 8; cb++) {
                    int c = (colg & 127) + cb*8 + 2*m;
                    Os[(c    )*132 + r0    ] = o[rb][cb][0] * iv0;
                    Os[(c + 1)*132 + r0    ] = o[rb][cb][1] * iv0;
                    Os[(c    )*132 + r0 + 8] = o[rb][cb][2] * iv1;
                    Os[(c + 1)*132 + r0 + 8] = o[rb][cb][3] * iv1;
                }
            }
        }
        __syncthreads();
        #pragma unroll 4
        for (int k = 0; k < 16; k++) {
            int c = k*8 + c0;
            size_t gi = (size_t)(h2*128 + c)*Nn + r4;
            float4 ov = *(const float4*)(Os + c*132 + r4);
            float4 xv = *(const float4*)(xb + gi);
            ov.x += xv.x; ov.y += xv.y; ov.z += xv.z; ov.w += xv.w;
            *(float4*)(ob + gi) = ov;
        }
    }
}

// ---------------------------------------------------------------------------
extern "C" void kernel_launch(void* const* d_in, const int* in_sizes, int n_in,
                              void* d_out, int out_size)
{
    const float* x  = (const float*)d_in[0];
    const float* Wq = (const float*)d_in[1];
    const float* bq = (const float*)d_in[2];
    const float* Wk = (const float*)d_in[3];
    const float* bk = (const float*)d_in[4];
    const float* Wv = (const float*)d_in[5];
    const float* bv = (const float*)d_in[6];
    float* out = (float*)d_out;

    cudaFuncSetAttribute(attn_kernel, cudaFuncAttributeMaxDynamicSharedMemorySize, SM_BYTES);
    proj_kernel<<<dim3(Nn/128, 5, Bc), 256>>>(x, Wq, bq, Wk, bk, Wv, bv);
    attn_kernel<<<dim3(Nn/128, Bc), 256, SM_BYTES>>>(x, out);
}